// round 5
// baseline (speedup 1.0000x reference)
#include <cuda_runtime.h>
#include <cstdint>
#include <cmath>

// Problem constants
#define BSZ 2
#define PP 512
#define NN 2048
#define DD 768
#define HH 12
#define HD 64
#define ROWS (NN + PP)          // 2560
#define MTOT (BSZ * ROWS)       // 5120
#define QKV3 (3 * DD)           // 2304

// Scratch (allocation-free rule: __device__ globals)
__device__ float g_qkv[(size_t)MTOT * QKV3];   // [b*2560+r][2304]
__device__ float g_attn[(size_t)MTOT * DD];    // [b*2560+r][768]
__device__ uint8_t g_mask[BSZ * PP];           // canonicalized xs_mask

// ---------------------------------------------------------------------------
// Mask canonicalization: the harness may upload the bool xs_mask as 1-byte
// bool, int32, or float32. Detect from the first 256 words (1024 bytes is
// in-bounds for every candidate) and convert to uint8 0/1.
//   - packed bool bytes: some word outside {0,1,0x3F800000} (prob ~ 1)
//   - int32: every word is exactly 0 or 1
//   - float32: words are 0 or 0x3F800000
// ---------------------------------------------------------------------------
__global__ void mask_convert(const uint32_t* __restrict__ mw)
{
    __shared__ int is_bool;
    const int tid = threadIdx.x;
    if (tid == 0) is_bool = 0;
    __syncthreads();
    if (tid < 256) {
        uint32_t w = mw[tid];
        if (w > 1u && w != 0x3F800000u) atomicOr(&is_bool, 1);
    }
    __syncthreads();
    if (is_bool) {
        g_mask[tid] = (((const uint8_t*)mw)[tid] != 0) ? 1 : 0;
    } else {
        // int32 or float32: word-nonzero test works for both
        g_mask[tid] = (mw[tid] != 0u) ? 1 : 0;
    }
}

// ---------------------------------------------------------------------------
// GEMM 1: full_qkv = concat(xq, xs) @ qkv_w + qkv_b
// M=5120, K=768, N=2304. 128x128 tile, BK=8, 256 threads, 8x8 per thread.
// ---------------------------------------------------------------------------
__global__ __launch_bounds__(256) void gemm_qkv(
    const float* __restrict__ xs, const float* __restrict__ xq,
    const float* __restrict__ w, const float* __restrict__ bias)
{
    __shared__ float As[8][128];
    __shared__ float Bs[8][128];
    const int tid = threadIdx.x;
    const int bx = blockIdx.x, by = blockIdx.y;

    const int a_row = tid >> 1;            // 0..127
    const int a_col = (tid & 1) * 4;       // 0 or 4
    const int b_row = tid >> 5;            // 0..7
    const int b_col = (tid & 31) * 4;      // 0..124

    // Virtual concat: rows [0,N) are xq, rows [N,N+P) are xs
    const int g = by * 128 + a_row;
    const int bb = g / ROWS, r = g % ROWS;
    const float* arow = (r < NN) ? (xq + ((size_t)bb * NN + r) * DD)
                                 : (xs + ((size_t)bb * PP + (r - NN)) * DD);
    const float* bptr = w + (size_t)b_row * QKV3 + bx * 128 + b_col;

    float acc[8][8];
#pragma unroll
    for (int i = 0; i < 8; i++)
#pragma unroll
        for (int j = 0; j < 8; j++) acc[i][j] = 0.0f;

    const int ty = tid >> 4, tx = tid & 15;

    for (int k0 = 0; k0 < DD; k0 += 8) {
        float4 av = *(const float4*)(arow + k0 + a_col);
        As[a_col + 0][a_row] = av.x;
        As[a_col + 1][a_row] = av.y;
        As[a_col + 2][a_row] = av.z;
        As[a_col + 3][a_row] = av.w;
        *(float4*)&Bs[b_row][b_col] = *(const float4*)(bptr + (size_t)k0 * QKV3);
        __syncthreads();
#pragma unroll
        for (int k = 0; k < 8; k++) {
            float4 a0 = *(const float4*)&As[k][ty * 8];
            float4 a1 = *(const float4*)&As[k][ty * 8 + 4];
            float4 b0 = *(const float4*)&Bs[k][tx * 8];
            float4 b1 = *(const float4*)&Bs[k][tx * 8 + 4];
            float af[8] = {a0.x, a0.y, a0.z, a0.w, a1.x, a1.y, a1.z, a1.w};
            float bf[8] = {b0.x, b0.y, b0.z, b0.w, b1.x, b1.y, b1.z, b1.w};
#pragma unroll
            for (int i = 0; i < 8; i++)
#pragma unroll
                for (int j = 0; j < 8; j++)
                    acc[i][j] = fmaf(af[i], bf[j], acc[i][j]);
        }
        __syncthreads();
    }

#pragma unroll
    for (int i = 0; i < 8; i++) {
        const int grow = by * 128 + ty * 8 + i;
        float* dst = g_qkv + (size_t)grow * QKV3 + bx * 128 + tx * 8;
#pragma unroll
        for (int j = 0; j < 8; j += 4) {
            const int col = bx * 128 + tx * 8 + j;
            float4 v;
            v.x = acc[i][j + 0] + __ldg(&bias[col + 0]);
            v.y = acc[i][j + 1] + __ldg(&bias[col + 1]);
            v.z = acc[i][j + 2] + __ldg(&bias[col + 2]);
            v.w = acc[i][j + 3] + __ldg(&bias[col + 3]);
            *(float4*)(dst + j) = v;
        }
    }
}

// ---------------------------------------------------------------------------
// Flash attention over g_qkv rows. Q rows = [q_start, q_start+Lq),
// KV rows = [0, Lk). Mask: kv index m < P && g_mask[b][m] -> -inf.
// Block: 64 queries, 256 threads (16x16), d=64, BKV=64. Online softmax with
// warp-shuffle row reductions (rows owned by 16-lane tx groups).
// ---------------------------------------------------------------------------
struct AttnSmem {
    float Qt[HD][68];                 // Q transposed (k-major), padded
    union {
        float Kt[HD][68];             // K transposed (k-major), padded
        float Ss[64][64];             // softmax probs (aliases Kt after use)
    } u;
    float Vs[64][HD];                 // V row-major
};

__global__ __launch_bounds__(256) void attn_kernel(int q_start, int Lk, int self_mode)
{
    extern __shared__ char smem_raw[];
    AttnSmem& sm = *reinterpret_cast<AttnSmem*>(smem_raw);

    const int tid = threadIdx.x;
    const int h = blockIdx.y, b = blockIdx.z;
    const int q0 = blockIdx.x * 64;
    const int ty = tid >> 4, tx = tid & 15;

    // Load Q tile transposed: Qt[c][r] = Q[r][c]
    const float* qbase = g_qkv + ((size_t)(b * ROWS + q_start + q0)) * QKV3 + h * HD;
    for (int idx = tid; idx < 64 * 16; idx += 256) {
        const int rr = idx >> 4;
        const int cc = (idx & 15) * 4;
        float4 v = *(const float4*)(qbase + (size_t)rr * QKV3 + cc);
        sm.Qt[cc + 0][rr] = v.x;
        sm.Qt[cc + 1][rr] = v.y;
        sm.Qt[cc + 2][rr] = v.z;
        sm.Qt[cc + 3][rr] = v.w;
    }

    float m_i[4], l_i[4], acc[4][4];
#pragma unroll
    for (int i = 0; i < 4; i++) {
        m_i[i] = -INFINITY;
        l_i[i] = 0.0f;
#pragma unroll
        for (int j = 0; j < 4; j++) acc[i][j] = 0.0f;
    }

    const float scale = 0.125f;   // 1/sqrt(64)
    const uint8_t* mrow = g_mask + (size_t)b * PP;

    for (int kv0 = 0; kv0 < Lk; kv0 += 64) {
        __syncthreads();   // guard smem reuse vs previous iteration's PV / Q load
        const float* kbase = g_qkv + ((size_t)(b * ROWS + kv0)) * QKV3 + DD + h * HD;
        const float* vbase = kbase + DD;
        for (int idx = tid; idx < 64 * 16; idx += 256) {
            const int mm = idx >> 4;
            const int cc = (idx & 15) * 4;
            float4 kv = *(const float4*)(kbase + (size_t)mm * QKV3 + cc);
            sm.u.Kt[cc + 0][mm] = kv.x;
            sm.u.Kt[cc + 1][mm] = kv.y;
            sm.u.Kt[cc + 2][mm] = kv.z;
            sm.u.Kt[cc + 3][mm] = kv.w;
            *(float4*)&sm.Vs[mm][cc] = *(const float4*)(vbase + (size_t)mm * QKV3 + cc);
        }
        __syncthreads();

        // S = Q @ K^T  (4x4 fragment per thread)
        float s[4][4];
#pragma unroll
        for (int i = 0; i < 4; i++)
#pragma unroll
            for (int j = 0; j < 4; j++) s[i][j] = 0.0f;
#pragma unroll 16
        for (int k = 0; k < HD; k++) {
            float4 aq = *(const float4*)&sm.Qt[k][ty * 4];
            float4 bk = *(const float4*)&sm.u.Kt[k][tx * 4];
            float af[4] = {aq.x, aq.y, aq.z, aq.w};
            float bf[4] = {bk.x, bk.y, bk.z, bk.w};
#pragma unroll
            for (int i = 0; i < 4; i++)
#pragma unroll
                for (int j = 0; j < 4; j++)
                    s[i][j] = fmaf(af[i], bf[j], s[i][j]);
        }

        // Mask (BEFORE scale, matching where(mask,-inf,scores)*scale) then scale
#pragma unroll
        for (int j = 0; j < 4; j++) {
            const int m = kv0 + tx * 4 + j;
            const bool msk = (m < PP) && (mrow[m] != 0);
#pragma unroll
            for (int i = 0; i < 4; i++)
                s[i][j] = msk ? -INFINITY : s[i][j] * scale;
        }

        // Online softmax: row reductions over the 16-lane tx group via shuffles
#pragma unroll
        for (int i = 0; i < 4; i++) {
            float rm = fmaxf(fmaxf(s[i][0], s[i][1]), fmaxf(s[i][2], s[i][3]));
#pragma unroll
            for (int off = 8; off >= 1; off >>= 1)
                rm = fmaxf(rm, __shfl_xor_sync(0xffffffffu, rm, off));
            const float nm = fmaxf(m_i[i], rm);
            const float nms = (nm == -INFINITY) ? 0.0f : nm;
            const float fac = __expf(m_i[i] - nms);
            m_i[i] = nm;
            float rs = 0.0f;
#pragma unroll
            for (int j = 0; j < 4; j++) {
                const float p = __expf(s[i][j] - nms);
                s[i][j] = p;
                rs += p;
                acc[i][j] *= fac;
            }
#pragma unroll
            for (int off = 8; off >= 1; off >>= 1)
                rs += __shfl_xor_sync(0xffffffffu, rs, off);
            l_i[i] = l_i[i] * fac + rs;
        }

        __syncthreads();   // all Kt reads done before aliased Ss writes
#pragma unroll
        for (int i = 0; i < 4; i++) {
            float4 pv = make_float4(s[i][0], s[i][1], s[i][2], s[i][3]);
            *(float4*)&sm.u.Ss[ty * 4 + i][tx * 4] = pv;
        }
        __syncthreads();

        // O += P~ @ V
#pragma unroll 4
        for (int kk0 = 0; kk0 < 64; kk0 += 4) {
            float4 vv[4];
#pragma unroll
            for (int t = 0; t < 4; t++)
                vv[t] = *(const float4*)&sm.Vs[kk0 + t][tx * 4];
#pragma unroll
            for (int i = 0; i < 4; i++) {
                float4 av = *(const float4*)&sm.u.Ss[ty * 4 + i][kk0];
                float af[4] = {av.x, av.y, av.z, av.w};
#pragma unroll
                for (int t = 0; t < 4; t++) {
                    acc[i][0] = fmaf(af[t], vv[t].x, acc[i][0]);
                    acc[i][1] = fmaf(af[t], vv[t].y, acc[i][1]);
                    acc[i][2] = fmaf(af[t], vv[t].z, acc[i][2]);
                    acc[i][3] = fmaf(af[t], vv[t].w, acc[i][3]);
                }
            }
        }
    }

    // Finalize + write
    if (!self_mode) {
        // cross: attn row = q_start + n, col = h*64 + d (standard layout)
#pragma unroll
        for (int i = 0; i < 4; i++) {
            const float inv = 1.0f / l_i[i];
            const int row_attn = q_start + q0 + ty * 4 + i;
            float4 v = make_float4(acc[i][0] * inv, acc[i][1] * inv,
                                   acc[i][2] * inv, acc[i][3] * inv);
            *(float4*)(g_attn + ((size_t)(b * ROWS + row_attn)) * DD + h * HD + tx * 4) = v;
        }
    } else {
        // self: scrambled transpose(-2,-1).view scatter
#pragma unroll
        for (int i = 0; i < 4; i++) {
            const float inv = 1.0f / l_i[i];
            const int p = q0 + ty * 4 + i;
#pragma unroll
            for (int j = 0; j < 4; j++) {
                const int k = tx * 4 + j;
                const int f = (h * HD + k) * PP + p;
                const int row = f / DD, col = f % DD;
                g_attn[((size_t)(b * ROWS + row)) * DD + col] = acc[i][j] * inv;
            }
        }
    }
}

// ---------------------------------------------------------------------------
// GEMM 2: out = g_attn @ proj_w + proj_b, scattered into the tuple output:
// [out_xs flat (2,512,768)] then [out_xq flat (2,2048,768)]
// ---------------------------------------------------------------------------
__global__ __launch_bounds__(256) void gemm_proj(
    const float* __restrict__ w, const float* __restrict__ bias,
    float* __restrict__ out)
{
    __shared__ float As[8][128];
    __shared__ float Bs[8][128];
    const int tid = threadIdx.x;
    const int bx = blockIdx.x, by = blockIdx.y;

    const int a_row = tid >> 1;
    const int a_col = (tid & 1) * 4;
    const int b_row = tid >> 5;
    const int b_col = (tid & 31) * 4;

    const float* arow = g_attn + ((size_t)(by * 128 + a_row)) * DD;
    const float* bptr = w + (size_t)b_row * DD + bx * 128 + b_col;

    float acc[8][8];
#pragma unroll
    for (int i = 0; i < 8; i++)
#pragma unroll
        for (int j = 0; j < 8; j++) acc[i][j] = 0.0f;

    const int ty = tid >> 4, tx = tid & 15;

    for (int k0 = 0; k0 < DD; k0 += 8) {
        float4 av = *(const float4*)(arow + k0 + a_col);
        As[a_col + 0][a_row] = av.x;
        As[a_col + 1][a_row] = av.y;
        As[a_col + 2][a_row] = av.z;
        As[a_col + 3][a_row] = av.w;
        *(float4*)&Bs[b_row][b_col] = *(const float4*)(bptr + (size_t)k0 * DD);
        __syncthreads();
#pragma unroll
        for (int k = 0; k < 8; k++) {
            float4 a0 = *(const float4*)&As[k][ty * 8];
            float4 a1 = *(const float4*)&As[k][ty * 8 + 4];
            float4 b0 = *(const float4*)&Bs[k][tx * 8];
            float4 b1 = *(const float4*)&Bs[k][tx * 8 + 4];
            float af[8] = {a0.x, a0.y, a0.z, a0.w, a1.x, a1.y, a1.z, a1.w};
            float bf[8] = {b0.x, b0.y, b0.z, b0.w, b1.x, b1.y, b1.z, b1.w};
#pragma unroll
            for (int i = 0; i < 8; i++)
#pragma unroll
                for (int j = 0; j < 8; j++)
                    acc[i][j] = fmaf(af[i], bf[j], acc[i][j]);
        }
        __syncthreads();
    }

#pragma unroll
    for (int i = 0; i < 8; i++) {
        const int g = by * 128 + ty * 8 + i;
        const int b = g / ROWS, r = g % ROWS;
        float* dst = (r < PP)
            ? out + ((size_t)b * PP + r) * DD
            : out + (size_t)BSZ * PP * DD + ((size_t)b * NN + (r - PP)) * DD;
#pragma unroll
        for (int j = 0; j < 8; j += 4) {
            const int col = bx * 128 + tx * 8 + j;
            float4 v;
            v.x = acc[i][j + 0] + __ldg(&bias[col + 0]);
            v.y = acc[i][j + 1] + __ldg(&bias[col + 1]);
            v.z = acc[i][j + 2] + __ldg(&bias[col + 2]);
            v.w = acc[i][j + 3] + __ldg(&bias[col + 3]);
            *(float4*)(dst + col) = v;
        }
    }
}

// ---------------------------------------------------------------------------
extern "C" void kernel_launch(void* const* d_in, const int* in_sizes, int n_in,
                              void* d_out, int out_size)
{
    const float*    xs     = (const float*)d_in[0];
    const float*    xq     = (const float*)d_in[1];
    const uint32_t* mask   = (const uint32_t*)d_in[2];
    const float*    qkv_w  = (const float*)d_in[3];
    const float*    qkv_b  = (const float*)d_in[4];
    const float*    proj_w = (const float*)d_in[5];
    const float*    proj_b = (const float*)d_in[6];
    float*          out    = (float*)d_out;

    (void)in_sizes; (void)n_in; (void)out_size;

    cudaFuncSetAttribute(attn_kernel, cudaFuncAttributeMaxDynamicSharedMemorySize,
                         (int)sizeof(AttnSmem));

    // 0) Canonicalize the mask (dtype auto-detect: bool8 / int32 / float32)
    mask_convert<<<1, BSZ * PP>>>(mask);

    // 1) QKV projection over virtual concat(xq, xs)
    gemm_qkv<<<dim3(QKV3 / 128, MTOT / 128), 256>>>(xs, xq, qkv_w, qkv_b);

    // 2) Cross attention: Q rows [P, P+N), KV rows [0, P+N)
    attn_kernel<<<dim3(NN / 64, HH, BSZ), 256, sizeof(AttnSmem)>>>(PP, ROWS, 0);

    // 3) Self attention: Q rows [0, P), KV rows [0, P) (scrambled output scatter)
    attn_kernel<<<dim3(PP / 64, HH, BSZ), 256, sizeof(AttnSmem)>>>(0, PP, 1);

    // 4) Output projection + tuple-layout scatter
    gemm_proj<<<dim3(DD / 128, MTOT / 128), 256>>>(proj_w, proj_b, out);
}